// round 16
// baseline (speedup 1.0000x reference)
#include <cuda_runtime.h>
#include <cuda_fp16.h>
#include <math.h>

#define BATCH 4
#define SEQ   1024
#define DIM   1024
#define NH    16
#define HDIM  64
#define MROWS (BATCH*SEQ)   /* 4096 */
#define NCOLS (3*DIM)       /* 3072 */
#define QSCALE_LOG2E 0.18033688011f  /* 0.125 * log2(e) */

typedef unsigned long long ull;

// ---------------- warp-MMA helpers (baseline sm_80 features only) ----------------
__device__ __forceinline__ unsigned smem_u32(const void* p) {
    unsigned a;
    asm("{ .reg .u64 t; cvta.to.shared.u64 t, %1; cvt.u32.u64 %0, t; }" : "=r"(a) : "l"(p));
    return a;
}
__device__ __forceinline__ void ldm_x4(unsigned* r, unsigned addr) {
    asm volatile("ldmatrix.sync.aligned.m8n8.x4.shared.b16 {%0,%1,%2,%3}, [%4];"
        : "=r"(r[0]), "=r"(r[1]), "=r"(r[2]), "=r"(r[3]) : "r"(addr));
}
__device__ __forceinline__ void ldm_x4t(unsigned* r, unsigned addr) {
    asm volatile("ldmatrix.sync.aligned.m8n8.x4.trans.shared.b16 {%0,%1,%2,%3}, [%4];"
        : "=r"(r[0]), "=r"(r[1]), "=r"(r[2]), "=r"(r[3]) : "r"(addr));
}
__device__ __forceinline__ void mma16816h(float* c, const unsigned* a, unsigned b0, unsigned b1) {
    asm volatile("mma.sync.aligned.m16n8k16.row.col.f32.f16.f16.f32 "
        "{%0,%1,%2,%3}, {%4,%5,%6,%7}, {%8,%9}, {%0,%1,%2,%3};"
        : "+f"(c[0]), "+f"(c[1]), "+f"(c[2]), "+f"(c[3])
        : "r"(a[0]), "r"(a[1]), "r"(a[2]), "r"(a[3]), "r"(b0), "r"(b1));
}
__device__ __forceinline__ void cp16(unsigned dst, const void* src) {
    asm volatile("cp.async.cg.shared.global [%0], [%1], 16;" :: "r"(dst), "l"(src));
}
#define CP_COMMIT() asm volatile("cp.async.commit_group;" ::: "memory")
#define CP_WAIT(n)  asm volatile("cp.async.wait_group %0;" :: "n"(n) : "memory")

// pack two f32 -> f16x2 (first arg -> upper half)
__device__ __forceinline__ unsigned hpack(float hi, float lo) {
    unsigned r; asm("cvt.rn.f16x2.f32 %0, %1, %2;" : "=r"(r) : "f"(hi), "f"(lo)); return r;
}
__device__ __forceinline__ float hhi(unsigned u) {
    return __half2float(__ushort_as_half((unsigned short)(u >> 16)));
}
__device__ __forceinline__ float hlo(unsigned u) {
    return __half2float(__ushort_as_half((unsigned short)(u & 0xffffu)));
}
__device__ __forceinline__ float ex2f(float x) {
    float y; asm("ex2.approx.ftz.f32 %0, %1;" : "=f"(y) : "f"(x)); return y;
}

// ---------------- global scratch (all fp16) ----------------
__device__ unsigned short g_xh[(size_t)MROWS * DIM];     // X fp16 (single)
__device__ unsigned short g_wth[(size_t)NCOLS * DIM];    // W^T fp16 (single)
// per-head layout [(b*16+h)*1024 + s][d]. Q pre-scaled by 0.125*log2e.
__device__ unsigned short g_qh[(size_t)MROWS * DIM];
__device__ unsigned short g_ql[(size_t)MROWS * DIM];
__device__ unsigned short g_kh[(size_t)MROWS * DIM];
__device__ unsigned short g_kl[(size_t)MROWS * DIM];
__device__ unsigned short g_vh[(size_t)MROWS * DIM];     // V single fp16

// ---------------------------------------------------------------------------
// Convert X -> fp16 (single)
// ---------------------------------------------------------------------------
__global__ __launch_bounds__(256) void xconv_kernel(const float* __restrict__ X)
{
    size_t i = ((size_t)blockIdx.x * 256 + threadIdx.x) * 4;
    float4 v = *(const float4*)(X + i);
    uint2 hv = make_uint2(hpack(v.y, v.x), hpack(v.w, v.z));
    *(uint2*)(g_xh + i) = hv;
}

// ---------------------------------------------------------------------------
// Transpose + convert W [1024][3072] -> W^T fp16 [3072][1024] (single)
// ---------------------------------------------------------------------------
__global__ __launch_bounds__(256) void wconv_kernel(const float* __restrict__ W)
{
    __shared__ float t[32][33];
    const int n0 = blockIdx.x * 32;
    const int k0 = blockIdx.y * 32;
    const int tx = threadIdx.x & 31;
    const int ty = threadIdx.x >> 5;
    #pragma unroll
    for (int i = 0; i < 4; i++)
        t[ty + 8 * i][tx] = W[(size_t)(k0 + ty + 8 * i) * NCOLS + n0 + tx];
    __syncthreads();
    #pragma unroll
    for (int i = 0; i < 4; i++) {
        float v = t[tx][ty + 8 * i];
        g_wth[(size_t)(n0 + ty + 8 * i) * DIM + k0 + tx] =
            __half_as_ushort(__float2half_rn(v));
    }
}

// ---------------------------------------------------------------------------
// QKV GEMM via HMMA fp16, SINGLE-TERM (X,W both fp16). CTA 256x128, 512 thr,
// 4-stage cp.async pipeline. Epilogue writes per-head fp16 Q(h,l) K(h,l) V(h).
// ---------------------------------------------------------------------------
#define ROWB    80
#define ATILE_B (256 * ROWB)             /* 20480 */
#define BTILE_B (128 * ROWB)             /* 10240 */
#define STG_B   (ATILE_B + BTILE_B)      /* 30720 */
#define GEMM_SMEM (4 * STG_B)            /* 122880 */

__global__ __launch_bounds__(512, 1) void qkv_mma_kernel(const float* __restrict__ bias)
{
    extern __shared__ __align__(128) char smem[];
    const unsigned sb = smem_u32(smem);
    const int tid  = threadIdx.x;
    const int wid  = tid >> 5;
    const int lane = tid & 31;

    const int m0 = blockIdx.y * 256;
    const int n0 = blockIdx.x * 128;
    const int wm = (wid & 3) * 64;
    const int wn = (wid >> 2) * 32;

    float acc[4][4][4];
    #pragma unroll
    for (int i = 0; i < 4; i++)
        #pragma unroll
        for (int j = 0; j < 4; j++)
            #pragma unroll
            for (int r = 0; r < 4; r++) acc[i][j][r] = 0.f;

    auto load_stage = [&](int c, int buf) {
        const unsigned base = sb + buf * STG_B;
        const int k0 = c * 32;
        // A: 256 rows x 32 fp16
        {
            const unsigned short* s_ = g_xh + (size_t)m0 * DIM + k0;
            #pragma unroll
            for (int it = 0; it < 2; it++) {
                int idx = tid + 512 * it;
                int row = idx >> 2, c8 = idx & 3;
                cp16(base + row * ROWB + c8 * 16, s_ + (size_t)row * DIM + c8 * 8);
            }
        }
        // B: 128 rows x 32 fp16
        {
            const unsigned short* s_ = g_wth + (size_t)n0 * DIM + k0;
            int row = tid >> 2, c8 = tid & 3;
            cp16(base + ATILE_B + row * ROWB + c8 * 16, s_ + (size_t)row * DIM + c8 * 8);
        }
    };

    load_stage(0, 0); CP_COMMIT();
    load_stage(1, 1); CP_COMMIT();
    load_stage(2, 2); CP_COMMIT();

    for (int c = 0; c < 32; c++) {
        if (c < 30)      { CP_WAIT(2); }
        else if (c == 30){ CP_WAIT(1); }
        else             { CP_WAIT(0); }
        __syncthreads();

        const int buf = c & 3;
        const unsigned sA = sb + buf * STG_B;
        const unsigned sB = sA + ATILE_B;

        #pragma unroll
        for (int k16 = 0; k16 < 2; k16++) {
            const int bmat = lane >> 3;
            const unsigned b_off = (wn + (bmat >> 1) * 8 + (lane & 7)) * ROWB
                                 + (k16 * 16 + (bmat & 1) * 8) * 2;
            unsigned bh[2][4];
            #pragma unroll
            for (int nt2 = 0; nt2 < 2; nt2++)
                ldm_x4(bh[nt2], sB + b_off + nt2 * 16 * ROWB);
            const unsigned a_off = (wm + (lane & 15)) * ROWB + (k16 * 16 + (lane >> 4) * 8) * 2;
            #pragma unroll
            for (int mt = 0; mt < 4; mt++) {
                unsigned ah[4];
                ldm_x4(ah, sA + a_off + mt * 16 * ROWB);
                #pragma unroll
                for (int nt = 0; nt < 4; nt++) {
                    const int n2 = nt >> 1, hb = (nt & 1) * 2;
                    mma16816h(acc[mt][nt], ah, bh[n2][hb], bh[n2][hb + 1]);
                }
            }
        }

        if (c + 3 < 32) {
            load_stage(c + 3, (c + 3) & 3);
            CP_COMMIT();
        }
    }

    // ---- epilogue: bias (+Q scale incl log2e), fp16 split, per-head store ----
    #pragma unroll
    for (int mt = 0; mt < 4; mt++) {
        const int row  = m0 + wm + mt * 16 + (lane >> 2);
        const int bidx = row >> 10;
        const int srow = row & 1023;
        #pragma unroll
        for (int nt = 0; nt < 4; nt++) {
            const int col    = n0 + wn + nt * 8 + (lane & 3) * 2;
            const int region = col >> 10;           // uniform per CTA
            const int hidx   = (col >> 6) & 15;
            const int d      = col & 63;
            const float sc = (region == 0) ? QSCALE_LOG2E : 1.f;
            const float b0 = bias[col], b1 = bias[col + 1];
            float x0 = (acc[mt][nt][0] + b0) * sc;
            float x1 = (acc[mt][nt][1] + b1) * sc;
            float y0 = (acc[mt][nt][2] + b0) * sc;
            float y1 = (acc[mt][nt][3] + b1) * sc;
            unsigned short* ph = (region == 0) ? g_qh : (region == 1) ? g_kh : g_vh;
            size_t o  = (((size_t)bidx * 16 + hidx) * 1024 + srow) * 64 + d;
            size_t o2 = o + 8 * 64;
            unsigned hx = hpack(x1, x0);
            unsigned hy = hpack(y1, y0);
            *(unsigned*)(ph + o)  = hx;
            *(unsigned*)(ph + o2) = hy;
            if (region < 2) {   // Q and K get a lo residual; V single fp16
                unsigned short* pl = (region == 0) ? g_ql : g_kl;
                unsigned lx = hpack(x1 - hhi(hx), x0 - hlo(hx));
                unsigned ly = hpack(y1 - hhi(hy), y0 - hlo(hy));
                *(unsigned*)(pl + o)  = lx;
                *(unsigned*)(pl + o2) = ly;
            }
        }
    }
}

// ---------------------------------------------------------------------------
// Tensor-core flash attention, fp16. QK^T 3-term (protects softmax); PV
// single-term (P,V fp16). Base-2 softmax; row-sum l via ones-MMA.
// CTA = 128 q-rows x one (b,h); KV tiles of 64; 2 CTA/SM.
// ---------------------------------------------------------------------------
#define ARB    144
#define TBA    (128 * ARB)               /* 18432 */
#define TBK    (64 * ARB)                /* 9216 */
#define KV_OFF (2 * TBA)                 /* after Qh, Ql */
#define KVBUF  (3 * TBK)                 /* Kh Kl Vh = 27648 */
#define MASK_OFF (KV_OFF + 2 * KVBUF)    /* 92160 */
#define ATTN_SMEM (MASK_OFF + 2 * 64 * 4)
#define HONES  0x3C003C00u               /* two fp16 1.0 */

__global__ __launch_bounds__(256, 2) void attn_mma_kernel(
    const int* __restrict__ mask, float* __restrict__ out)
{
    extern __shared__ __align__(128) char smem[];
    const unsigned sb = smem_u32(smem);
    float* maskf = (float*)(smem + MASK_OFF);

    const int q0 = blockIdx.x * 128;
    const int bh = blockIdx.y;
    const int b  = bh >> 4;
    const int h  = bh & 15;

    const int tid  = threadIdx.x;
    const int wid  = tid >> 5;
    const int lane = tid & 31;
    const int wq0  = wid * 16;

    const size_t hb_base = (size_t)bh * SEQ * HDIM;

    // ---- Q load (once): Qh at 0, Ql at TBA ----
    {
        const size_t qoff = hb_base + (size_t)q0 * HDIM;
        #pragma unroll
        for (int t = 0; t < 2; t++) {
            const unsigned short* src = (t ? g_ql : g_qh) + qoff;
            #pragma unroll
            for (int it = 0; it < 4; it++) {
                int idx = tid + 256 * it;
                int row = idx >> 3;
                int c16 = idx & 7;
                cp16(sb + t * TBA + row * ARB + c16 * 16, src + (size_t)row * HDIM + c16 * 8);
            }
        }
    }

    auto load_kv = [&](int kt, int buf) {
        const unsigned base = sb + KV_OFF + buf * KVBUF;
        const size_t o = hb_base + (size_t)kt * 64 * HDIM;
        const unsigned short* srcs[3] = { g_kh + o, g_kl + o, g_vh + o };
        #pragma unroll
        for (int t = 0; t < 3; t++) {
            #pragma unroll
            for (int it = 0; it < 2; it++) {
                int idx = tid + 256 * it;
                int row = idx >> 3;
                int c16 = idx & 7;
                cp16(base + t * TBK + row * ARB + c16 * 16,
                     srcs[t] + (size_t)row * HDIM + c16 * 8);
            }
        }
        if (tid < 64)
            maskf[buf * 64 + tid] = mask[b * SEQ + kt * 64 + tid] ? 0.f : -1e30f;
    };

    load_kv(0, 0);
    CP_COMMIT();

    float m0r = -INFINITY, m1r = -INFINITY;
    float accO[8][4];
    float accL[4] = {0.f, 0.f, 0.f, 0.f};
    #pragma unroll
    for (int i = 0; i < 8; i++)
        #pragma unroll
        for (int j = 0; j < 4; j++) accO[i][j] = 0.f;

    for (int kt = 0; kt < 16; kt++) {
        const int buf = kt & 1;
        if (kt + 1 < 16) {
            load_kv(kt + 1, buf ^ 1);
            CP_COMMIT();
            CP_WAIT(1);
        } else {
            CP_WAIT(0);
        }
        __syncthreads();

        const unsigned sKh = sb + KV_OFF + buf * KVBUF;
        const unsigned sVh = sKh + 2 * TBK;

        // ---- S = Q K^T (3-term fp16; scores in log2 domain) ----
        float s[8][4];
        #pragma unroll
        for (int i = 0; i < 8; i++)
            #pragma unroll
            for (int j = 0; j < 4; j++) s[i][j] = 0.f;

        const int bmat = lane >> 3;
        #pragma unroll
        for (int k16 = 0; k16 < 4; k16++) {
            const unsigned a_addr = sb + (wq0 + (lane & 15)) * ARB
                                  + (k16 * 16 + (lane >> 4) * 8) * 2;
            unsigned qh[4], ql[4];
            ldm_x4(qh, a_addr);
            ldm_x4(ql, a_addr + TBA);
            #pragma unroll
            for (int gp = 0; gp < 2; gp++) {
                unsigned kh[2][4], kl[2][4];
                #pragma unroll
                for (int g2 = 0; g2 < 2; g2++) {
                    const int g = gp * 2 + g2;
                    const unsigned b_addr = sKh
                        + (g * 16 + (bmat >> 1) * 8 + (lane & 7)) * ARB
                        + (k16 * 16 + (bmat & 1) * 8) * 2;
                    ldm_x4(kh[g2], b_addr);
                    ldm_x4(kl[g2], b_addr + TBK);
                }
                #pragma unroll
                for (int g2 = 0; g2 < 2; g2++) {
                    const int g = gp * 2 + g2;
                    mma16816h(s[2*g],   qh, kh[g2][0], kh[g2][1]);
                    mma16816h(s[2*g+1], qh, kh[g2][2], kh[g2][3]);
                }
                #pragma unroll
                for (int g2 = 0; g2 < 2; g2++) {
                    const int g = gp * 2 + g2;
                    mma16816h(s[2*g],   qh, kl[g2][0], kl[g2][1]);
                    mma16816h(s[2*g+1], qh, kl[g2][2], kl[g2][3]);
                }
                #pragma unroll
                for (int g2 = 0; g2 < 2; g2++) {
                    const int g = gp * 2 + g2;
                    mma16816h(s[2*g],   ql, kh[g2][0], kh[g2][1]);
                    mma16816h(s[2*g+1], ql, kh[g2][2], kh[g2][3]);
                }
            }
        }

        // ---- mask add ----
        const float* madd = maskf + buf * 64;
        #pragma unroll
        for (int t = 0; t < 8; t++) {
            float2 mm = *(const float2*)(madd + t * 8 + (lane & 3) * 2);
            s[t][0] += mm.x; s[t][1] += mm.y;
            s[t][2] += mm.x; s[t][3] += mm.y;
        }

        // ---- online softmax, base-2 ----
        float mx0 = -INFINITY, mx1 = -INFINITY;
        #pragma unroll
        for (int t = 0; t < 8; t++) {
            mx0 = fmaxf(mx0, fmaxf(s[t][0], s[t][1]));
            mx1 = fmaxf(mx1, fmaxf(s[t][2], s[t][3]));
        }
        mx0 = fmaxf(mx0, __shfl_xor_sync(0xffffffffu, mx0, 1));
        mx0 = fmaxf(mx0, __shfl_xor_sync(0xffffffffu, mx0, 2));
        mx1 = fmaxf(mx1, __shfl_xor_sync(0xffffffffu, mx1, 1));
        mx1 = fmaxf(mx1, __shfl_xor_sync(0xffffffffu, mx1, 2));

        const float mn0 = fmaxf(m0r, mx0);
        const float mn1 = fmaxf(m1r, mx1);
        const float a0 = ex2f(m0r - mn0);
        const float a1 = ex2f(m1r - mn1);
        m0r = mn0; m1r = mn1;

        #pragma unroll
        for (int t = 0; t < 8; t++) {
            s[t][0] = ex2f(s[t][0] - mn0);
            s[t][1] = ex2f(s[t][1] - mn0);
            s[t][2] = ex2f(s[t][2] - mn1);
            s[t][3] = ex2f(s[t][3] - mn1);
        }

        #pragma unroll
        for (int nt = 0; nt < 8; nt++) {
            accO[nt][0] *= a0; accO[nt][1] *= a0;
            accO[nt][2] *= a1; accO[nt][3] *= a1;
        }
        accL[0] *= a0; accL[1] *= a0;
        accL[2] *= a1; accL[3] *= a1;

        // ---- O += P V (single-term fp16), l += P @ 1 ----
        #pragma unroll
        for (int k16 = 0; k16 < 4; k16++) {
            unsigned ph[4];
            #pragma unroll
            for (int half = 0; half < 2; half++) {
                const float* sp = s[2 * k16 + half];
                ph[2 * half]     = hpack(sp[1], sp[0]);
                ph[2 * half + 1] = hpack(sp[3], sp[2]);
            }
            mma16816h(accL, ph, HONES, HONES);
            #pragma unroll
            for (int dp = 0; dp < 2; dp++) {
                unsigned vhf[2][4];
                #pragma unroll
                for (int d2 = 0; d2 < 2; d2++) {
                    const int dg = dp * 2 + d2;
                    const unsigned v_addr = sVh + (k16 * 16 + (lane & 15)) * ARB
                                          + (dg * 16 + (lane >> 4) * 8) * 2;
                    ldm_x4t(vhf[d2], v_addr);
                }
                #pragma unroll
                for (int d2 = 0; d2 < 2; d2++) {
                    const int dg = dp * 2 + d2;
                    mma16816h(accO[2*dg],   ph, vhf[d2][0], vhf[d2][1]);
                    mma16816h(accO[2*dg+1], ph, vhf[d2][2], vhf[d2][3]);
                }
            }
        }
        __syncthreads();
    }

    // ---- epilogue: normalize with MMA-computed l, store ----
    const float inv0 = 1.f / accL[0];
    const float inv1 = 1.f / accL[2];
    const int row = q0 + wq0 + (lane >> 2);
    float* orow0 = out + (size_t)(b * SEQ + row) * DIM + h * HDIM;
    float* orow1 = orow0 + 8 * DIM;
    #pragma unroll
    for (int nt = 0; nt < 8; nt++) {
        const int d = nt * 8 + (lane & 3) * 2;
        *(float2*)(orow0 + d) = make_float2(accO[nt][0] * inv0, accO[nt][1] * inv0);
        *(float2*)(orow1 + d) = make_float2(accO[nt][2] * inv1, accO[nt][3] * inv1);
    }
}

// ---------------------------------------------------------------------------
extern "C" void kernel_launch(void* const* d_in, const int* in_sizes, int n_in,
                              void* d_out, int out_size)
{
    const float* x    = (const float*)d_in[0];   // [4,1024,1024]
    const int*   mask = (const int*)  d_in[1];   // [4,1024]
    const float* W    = (const float*)d_in[2];   // [1024,3072]
    const float* bias = (const float*)d_in[3];   // [3072]
    float* out = (float*)d_out;                  // [4,1024,1024]

    cudaFuncSetAttribute(qkv_mma_kernel,
                         cudaFuncAttributeMaxDynamicSharedMemorySize, GEMM_SMEM);
    cudaFuncSetAttribute(attn_mma_kernel,
                         cudaFuncAttributeMaxDynamicSharedMemorySize, ATTN_SMEM);

    xconv_kernel<<<(MROWS * DIM) / (256 * 4), 256>>>(x);
    wconv_kernel<<<dim3(NCOLS / 32, DIM / 32), 256>>>(W);

    dim3 gg(NCOLS / 128, MROWS / 256);           // (24, 16)
    qkv_mma_kernel<<<gg, 512, GEMM_SMEM>>>(bias);

    dim3 ga(SEQ / 128, BATCH * NH);              // (8, 64)
    attn_mma_kernel<<<ga, 256, ATTN_SMEM>>>(mask, out);
}

// round 17
// speedup vs baseline: 1.5702x; 1.5702x over previous
#include <cuda_runtime.h>
#include <cuda_fp16.h>
#include <math.h>

#define BATCH 4
#define SEQ   1024
#define DIM   1024
#define NH    16
#define HDIM  64
#define MROWS (BATCH*SEQ)   /* 4096 */
#define NCOLS (3*DIM)       /* 3072 */
#define QSCALE_LOG2E 0.18033688011f  /* 0.125 * log2(e) */

typedef unsigned long long ull;

// ---------------- warp-MMA helpers (baseline sm_80 features only) ----------------
__device__ __forceinline__ unsigned smem_u32(const void* p) {
    unsigned a;
    asm("{ .reg .u64 t; cvta.to.shared.u64 t, %1; cvt.u32.u64 %0, t; }" : "=r"(a) : "l"(p));
    return a;
}
__device__ __forceinline__ void ldm_x4(unsigned* r, unsigned addr) {
    asm volatile("ldmatrix.sync.aligned.m8n8.x4.shared.b16 {%0,%1,%2,%3}, [%4];"
        : "=r"(r[0]), "=r"(r[1]), "=r"(r[2]), "=r"(r[3]) : "r"(addr));
}
__device__ __forceinline__ void ldm_x4t(unsigned* r, unsigned addr) {
    asm volatile("ldmatrix.sync.aligned.m8n8.x4.trans.shared.b16 {%0,%1,%2,%3}, [%4];"
        : "=r"(r[0]), "=r"(r[1]), "=r"(r[2]), "=r"(r[3]) : "r"(addr));
}
__device__ __forceinline__ void mma16816h(float* c, const unsigned* a, unsigned b0, unsigned b1) {
    asm volatile("mma.sync.aligned.m16n8k16.row.col.f32.f16.f16.f32 "
        "{%0,%1,%2,%3}, {%4,%5,%6,%7}, {%8,%9}, {%0,%1,%2,%3};"
        : "+f"(c[0]), "+f"(c[1]), "+f"(c[2]), "+f"(c[3])
        : "r"(a[0]), "r"(a[1]), "r"(a[2]), "r"(a[3]), "r"(b0), "r"(b1));
}
__device__ __forceinline__ void cp16(unsigned dst, const void* src) {
    asm volatile("cp.async.cg.shared.global [%0], [%1], 16;" :: "r"(dst), "l"(src));
}
#define CP_COMMIT() asm volatile("cp.async.commit_group;" ::: "memory")
#define CP_WAIT(n)  asm volatile("cp.async.wait_group %0;" :: "n"(n) : "memory")

// pack two f32 -> f16x2 (first arg -> upper half)
__device__ __forceinline__ unsigned hpack(float hi, float lo) {
    unsigned r; asm("cvt.rn.f16x2.f32 %0, %1, %2;" : "=r"(r) : "f"(hi), "f"(lo)); return r;
}
__device__ __forceinline__ float hhi(unsigned u) {
    return __half2float(__ushort_as_half((unsigned short)(u >> 16)));
}
__device__ __forceinline__ float hlo(unsigned u) {
    return __half2float(__ushort_as_half((unsigned short)(u & 0xffffu)));
}
__device__ __forceinline__ float ex2f(float x) {
    float y; asm("ex2.approx.ftz.f32 %0, %1;" : "=f"(y) : "f"(x)); return y;
}

// ---------------- global scratch (all fp16) ----------------
__device__ unsigned short g_xh[(size_t)MROWS * DIM];     // X fp16 (single)
__device__ unsigned short g_wth[(size_t)NCOLS * DIM];    // W^T fp16 (single)
// per-head layout [(b*16+h)*1024 + s][d]. Q pre-scaled by 0.125*log2e.
__device__ unsigned short g_qh[(size_t)MROWS * DIM];
__device__ unsigned short g_ql[(size_t)MROWS * DIM];
__device__ unsigned short g_kh[(size_t)MROWS * DIM];
__device__ unsigned short g_kl[(size_t)MROWS * DIM];
__device__ unsigned short g_vh[(size_t)MROWS * DIM];     // V single fp16

// ---------------------------------------------------------------------------
// Convert X -> fp16 (single)
// ---------------------------------------------------------------------------
__global__ __launch_bounds__(256) void xconv_kernel(const float* __restrict__ X)
{
    size_t i = ((size_t)blockIdx.x * 256 + threadIdx.x) * 4;
    float4 v = *(const float4*)(X + i);
    uint2 hv = make_uint2(hpack(v.y, v.x), hpack(v.w, v.z));
    *(uint2*)(g_xh + i) = hv;
}

// ---------------------------------------------------------------------------
// Transpose + convert W [1024][3072] -> W^T fp16 [3072][1024] (single)
// ---------------------------------------------------------------------------
__global__ __launch_bounds__(256) void wconv_kernel(const float* __restrict__ W)
{
    __shared__ float t[32][33];
    const int n0 = blockIdx.x * 32;
    const int k0 = blockIdx.y * 32;
    const int tx = threadIdx.x & 31;
    const int ty = threadIdx.x >> 5;
    #pragma unroll
    for (int i = 0; i < 4; i++)
        t[ty + 8 * i][tx] = W[(size_t)(k0 + ty + 8 * i) * NCOLS + n0 + tx];
    __syncthreads();
    #pragma unroll
    for (int i = 0; i < 4; i++) {
        float v = t[tx][ty + 8 * i];
        g_wth[(size_t)(n0 + ty + 8 * i) * DIM + k0 + tx] =
            __half_as_ushort(__float2half_rn(v));
    }
}

// ---------------------------------------------------------------------------
// QKV GEMM via HMMA fp16, SINGLE-TERM. CTA 128x128, 256 thr (8 warps, 2Mx4N),
// 4-stage cp.async pipeline, 80KB smem -> 2 CTAs/SM for cross-CTA overlap.
// ---------------------------------------------------------------------------
#define ROWB    80
#define GTILE_B (128 * ROWB)             /* 10240 per A or B tile */
#define STG_B   (2 * GTILE_B)            /* 20480 */
#define GEMM_SMEM (4 * STG_B)            /* 81920 */

__global__ __launch_bounds__(256, 2) void qkv_mma_kernel(const float* __restrict__ bias)
{
    extern __shared__ __align__(128) char smem[];
    const unsigned sb = smem_u32(smem);
    const int tid  = threadIdx.x;
    const int wid  = tid >> 5;
    const int lane = tid & 31;

    const int m0 = blockIdx.y * 128;
    const int n0 = blockIdx.x * 128;
    const int wm = (wid & 1) * 64;      // 2 m-warps
    const int wn = (wid >> 1) * 32;     // 4 n-warps

    float acc[4][4][4];
    #pragma unroll
    for (int i = 0; i < 4; i++)
        #pragma unroll
        for (int j = 0; j < 4; j++)
            #pragma unroll
            for (int r = 0; r < 4; r++) acc[i][j][r] = 0.f;

    auto load_stage = [&](int c, int buf) {
        const unsigned base = sb + buf * STG_B;
        const int k0 = c * 32;
        // A: 128 rows x 32 fp16 (512 cp16 over 256 threads)
        {
            const unsigned short* s_ = g_xh + (size_t)m0 * DIM + k0;
            #pragma unroll
            for (int it = 0; it < 2; it++) {
                int idx = tid + 256 * it;
                int row = idx >> 2, c8 = idx & 3;
                cp16(base + row * ROWB + c8 * 16, s_ + (size_t)row * DIM + c8 * 8);
            }
        }
        // B: 128 rows x 32 fp16
        {
            const unsigned short* s_ = g_wth + (size_t)n0 * DIM + k0;
            #pragma unroll
            for (int it = 0; it < 2; it++) {
                int idx = tid + 256 * it;
                int row = idx >> 2, c8 = idx & 3;
                cp16(base + GTILE_B + row * ROWB + c8 * 16, s_ + (size_t)row * DIM + c8 * 8);
            }
        }
    };

    load_stage(0, 0); CP_COMMIT();
    load_stage(1, 1); CP_COMMIT();
    load_stage(2, 2); CP_COMMIT();

    for (int c = 0; c < 32; c++) {
        if (c < 30)      { CP_WAIT(2); }
        else if (c == 30){ CP_WAIT(1); }
        else             { CP_WAIT(0); }
        __syncthreads();

        const int buf = c & 3;
        const unsigned sA = sb + buf * STG_B;
        const unsigned sB = sA + GTILE_B;

        #pragma unroll
        for (int k16 = 0; k16 < 2; k16++) {
            const int bmat = lane >> 3;
            const unsigned b_off = (wn + (bmat >> 1) * 8 + (lane & 7)) * ROWB
                                 + (k16 * 16 + (bmat & 1) * 8) * 2;
            unsigned bh[2][4];
            #pragma unroll
            for (int nt2 = 0; nt2 < 2; nt2++)
                ldm_x4(bh[nt2], sB + b_off + nt2 * 16 * ROWB);
            const unsigned a_off = (wm + (lane & 15)) * ROWB + (k16 * 16 + (lane >> 4) * 8) * 2;
            #pragma unroll
            for (int mt = 0; mt < 4; mt++) {
                unsigned ah[4];
                ldm_x4(ah, sA + a_off + mt * 16 * ROWB);
                #pragma unroll
                for (int nt = 0; nt < 4; nt++) {
                    const int n2 = nt >> 1, hb = (nt & 1) * 2;
                    mma16816h(acc[mt][nt], ah, bh[n2][hb], bh[n2][hb + 1]);
                }
            }
        }

        if (c + 3 < 32) {
            load_stage(c + 3, (c + 3) & 3);
            CP_COMMIT();
        }
    }

    // ---- epilogue: bias (+Q scale incl log2e), fp16 split, per-head store ----
    #pragma unroll
    for (int mt = 0; mt < 4; mt++) {
        const int row  = m0 + wm + mt * 16 + (lane >> 2);
        const int bidx = row >> 10;
        const int srow = row & 1023;
        #pragma unroll
        for (int nt = 0; nt < 4; nt++) {
            const int col    = n0 + wn + nt * 8 + (lane & 3) * 2;
            const int region = col >> 10;           // uniform per CTA
            const int hidx   = (col >> 6) & 15;
            const int d      = col & 63;
            const float sc = (region == 0) ? QSCALE_LOG2E : 1.f;
            const float b0 = bias[col], b1 = bias[col + 1];
            float x0 = (acc[mt][nt][0] + b0) * sc;
            float x1 = (acc[mt][nt][1] + b1) * sc;
            float y0 = (acc[mt][nt][2] + b0) * sc;
            float y1 = (acc[mt][nt][3] + b1) * sc;
            unsigned short* ph = (region == 0) ? g_qh : (region == 1) ? g_kh : g_vh;
            size_t o  = (((size_t)bidx * 16 + hidx) * 1024 + srow) * 64 + d;
            size_t o2 = o + 8 * 64;
            unsigned hx = hpack(x1, x0);
            unsigned hy = hpack(y1, y0);
            *(unsigned*)(ph + o)  = hx;
            *(unsigned*)(ph + o2) = hy;
            if (region < 2) {   // Q and K get a lo residual; V single fp16
                unsigned short* pl = (region == 0) ? g_ql : g_kl;
                unsigned lx = hpack(x1 - hhi(hx), x0 - hlo(hx));
                unsigned ly = hpack(y1 - hhi(hy), y0 - hlo(hy));
                *(unsigned*)(pl + o)  = lx;
                *(unsigned*)(pl + o2) = ly;
            }
        }
    }
}

// ---------------------------------------------------------------------------
// Tensor-core flash attention, fp16. QK^T 3-term (protects softmax); PV
// single-term (P,V fp16). Base-2 softmax; row-sum l via ones-MMA.
// CTA = 128 q-rows x one (b,h); KV tiles of 64; 2 CTA/SM.
// ---------------------------------------------------------------------------
#define ARB    144
#define TBA    (128 * ARB)               /* 18432 */
#define TBK    (64 * ARB)                /* 9216 */
#define KV_OFF (2 * TBA)                 /* after Qh, Ql */
#define KVBUF  (3 * TBK)                 /* Kh Kl Vh = 27648 */
#define MASK_OFF (KV_OFF + 2 * KVBUF)    /* 92160 */
#define ATTN_SMEM (MASK_OFF + 2 * 64 * 4)
#define HONES  0x3C003C00u               /* two fp16 1.0 */

__global__ __launch_bounds__(256, 2) void attn_mma_kernel(
    const int* __restrict__ mask, float* __restrict__ out)
{
    extern __shared__ __align__(128) char smem[];
    const unsigned sb = smem_u32(smem);
    float* maskf = (float*)(smem + MASK_OFF);

    const int q0 = blockIdx.x * 128;
    const int bh = blockIdx.y;
    const int b  = bh >> 4;
    const int h  = bh & 15;

    const int tid  = threadIdx.x;
    const int wid  = tid >> 5;
    const int lane = tid & 31;
    const int wq0  = wid * 16;

    const size_t hb_base = (size_t)bh * SEQ * HDIM;

    // ---- Q load (once): Qh at 0, Ql at TBA ----
    {
        const size_t qoff = hb_base + (size_t)q0 * HDIM;
        #pragma unroll
        for (int t = 0; t < 2; t++) {
            const unsigned short* src = (t ? g_ql : g_qh) + qoff;
            #pragma unroll
            for (int it = 0; it < 4; it++) {
                int idx = tid + 256 * it;
                int row = idx >> 3;
                int c16 = idx & 7;
                cp16(sb + t * TBA + row * ARB + c16 * 16, src + (size_t)row * HDIM + c16 * 8);
            }
        }
    }

    auto load_kv = [&](int kt, int buf) {
        const unsigned base = sb + KV_OFF + buf * KVBUF;
        const size_t o = hb_base + (size_t)kt * 64 * HDIM;
        const unsigned short* srcs[3] = { g_kh + o, g_kl + o, g_vh + o };
        #pragma unroll
        for (int t = 0; t < 3; t++) {
            #pragma unroll
            for (int it = 0; it < 2; it++) {
                int idx = tid + 256 * it;
                int row = idx >> 3;
                int c16 = idx & 7;
                cp16(base + t * TBK + row * ARB + c16 * 16,
                     srcs[t] + (size_t)row * HDIM + c16 * 8);
            }
        }
        if (tid < 64)
            maskf[buf * 64 + tid] = mask[b * SEQ + kt * 64 + tid] ? 0.f : -1e30f;
    };

    load_kv(0, 0);
    CP_COMMIT();

    float m0r = -INFINITY, m1r = -INFINITY;
    float accO[8][4];
    float accL[4] = {0.f, 0.f, 0.f, 0.f};
    #pragma unroll
    for (int i = 0; i < 8; i++)
        #pragma unroll
        for (int j = 0; j < 4; j++) accO[i][j] = 0.f;

    for (int kt = 0; kt < 16; kt++) {
        const int buf = kt & 1;
        if (kt + 1 < 16) {
            load_kv(kt + 1, buf ^ 1);
            CP_COMMIT();
            CP_WAIT(1);
        } else {
            CP_WAIT(0);
        }
        __syncthreads();

        const unsigned sKh = sb + KV_OFF + buf * KVBUF;
        const unsigned sVh = sKh + 2 * TBK;

        // ---- S = Q K^T (3-term fp16; scores in log2 domain) ----
        float s[8][4];
        #pragma unroll
        for (int i = 0; i < 8; i++)
            #pragma unroll
            for (int j = 0; j < 4; j++) s[i][j] = 0.f;

        const int bmat = lane >> 3;
        #pragma unroll
        for (int k16 = 0; k16 < 4; k16++) {
            const unsigned a_addr = sb + (wq0 + (lane & 15)) * ARB
                                  + (k16 * 16 + (lane >> 4) * 8) * 2;
            unsigned qh[4], ql[4];
            ldm_x4(qh, a_addr);
            ldm_x4(ql, a_addr + TBA);
            #pragma unroll
            for (int gp = 0; gp < 2; gp++) {
                unsigned kh[2][4], kl[2][4];
                #pragma unroll
                for (int g2 = 0; g2 < 2; g2++) {
                    const int g = gp * 2 + g2;
                    const unsigned b_addr = sKh
                        + (g * 16 + (bmat >> 1) * 8 + (lane & 7)) * ARB
                        + (k16 * 16 + (bmat & 1) * 8) * 2;
                    ldm_x4(kh[g2], b_addr);
                    ldm_x4(kl[g2], b_addr + TBK);
                }
                #pragma unroll
                for (int g2 = 0; g2 < 2; g2++) {
                    const int g = gp * 2 + g2;
                    mma16816h(s[2*g],   qh, kh[g2][0], kh[g2][1]);
                    mma16816h(s[2*g+1], qh, kh[g2][2], kh[g2][3]);
                }
                #pragma unroll
                for (int g2 = 0; g2 < 2; g2++) {
                    const int g = gp * 2 + g2;
                    mma16816h(s[2*g],   qh, kl[g2][0], kl[g2][1]);
                    mma16816h(s[2*g+1], qh, kl[g2][2], kl[g2][3]);
                }
                #pragma unroll
                for (int g2 = 0; g2 < 2; g2++) {
                    const int g = gp * 2 + g2;
                    mma16816h(s[2*g],   ql, kh[g2][0], kh[g2][1]);
                    mma16816h(s[2*g+1], ql, kh[g2][2], kh[g2][3]);
                }
            }
        }

        // ---- mask add ----
        const float* madd = maskf + buf * 64;
        #pragma unroll
        for (int t = 0; t < 8; t++) {
            float2 mm = *(const float2*)(madd + t * 8 + (lane & 3) * 2);
            s[t][0] += mm.x; s[t][1] += mm.y;
            s[t][2] += mm.x; s[t][3] += mm.y;
        }

        // ---- online softmax, base-2 ----
        float mx0 = -INFINITY, mx1 = -INFINITY;
        #pragma unroll
        for (int t = 0; t < 8; t++) {
            mx0 = fmaxf(mx0, fmaxf(s[t][0], s[t][1]));
            mx1 = fmaxf(mx1, fmaxf(s[t][2], s[t][3]));
        }
        mx0 = fmaxf(mx0, __shfl_xor_sync(0xffffffffu, mx0, 1));
        mx0 = fmaxf(mx0, __shfl_xor_sync(0xffffffffu, mx0, 2));
        mx1 = fmaxf(mx1, __shfl_xor_sync(0xffffffffu, mx1, 1));
        mx1 = fmaxf(mx1, __shfl_xor_sync(0xffffffffu, mx1, 2));

        const float mn0 = fmaxf(m0r, mx0);
        const float mn1 = fmaxf(m1r, mx1);
        const float a0 = ex2f(m0r - mn0);
        const float a1 = ex2f(m1r - mn1);
        m0r = mn0; m1r = mn1;

        #pragma unroll
        for (int t = 0; t < 8; t++) {
            s[t][0] = ex2f(s[t][0] - mn0);
            s[t][1] = ex2f(s[t][1] - mn0);
            s[t][2] = ex2f(s[t][2] - mn1);
            s[t][3] = ex2f(s[t][3] - mn1);
        }

        #pragma unroll
        for (int nt = 0; nt < 8; nt++) {
            accO[nt][0] *= a0; accO[nt][1] *= a0;
            accO[nt][2] *= a1; accO[nt][3] *= a1;
        }
        accL[0] *= a0; accL[1] *= a0;
        accL[2] *= a1; accL[3] *= a1;

        // ---- O += P V (single-term fp16), l += P @ 1 ----
        #pragma unroll
        for (int k16 = 0; k16 < 4; k16++) {
            unsigned ph[4];
            #pragma unroll
            for (int half = 0; half < 2; half++) {
                const float* sp = s[2 * k16 + half];
                ph[2 * half]     = hpack(sp[1], sp[0]);
                ph[2 * half + 1] = hpack(sp[3], sp[2]);
            }
            mma16816h(accL, ph, HONES, HONES);
            #pragma unroll
            for (int dp = 0; dp < 2; dp++) {
                unsigned vhf[2][4];
                #pragma unroll
                for (int d2 = 0; d2 < 2; d2++) {
                    const int dg = dp * 2 + d2;
                    const unsigned v_addr = sVh + (k16 * 16 + (lane & 15)) * ARB
                                          + (dg * 16 + (lane >> 4) * 8) * 2;
                    ldm_x4t(vhf[d2], v_addr);
                }
                #pragma unroll
                for (int d2 = 0; d2 < 2; d2++) {
                    const int dg = dp * 2 + d2;
                    mma16816h(accO[2*dg],   ph, vhf[d2][0], vhf[d2][1]);
                    mma16816h(accO[2*dg+1], ph, vhf[d2][2], vhf[d2][3]);
                }
            }
        }
        __syncthreads();
    }

    // ---- epilogue: normalize with MMA-computed l, store ----
    const float inv0 = 1.f / accL[0];
    const float inv1 = 1.f / accL[2];
    const int row = q0 + wq0 + (lane >> 2);
    float* orow0 = out + (size_t)(b * SEQ + row) * DIM + h * HDIM;
    float* orow1 = orow0 + 8 * DIM;
    #pragma unroll
    for (int nt = 0; nt < 8; nt++) {
        const int d = nt * 8 + (lane & 3) * 2;
        *(float2*)(orow0 + d) = make_float2(accO[nt][0] * inv0, accO[nt][1] * inv0);
        *(float2*)(orow1 + d) = make_float2(accO[nt][2] * inv1, accO[nt][3] * inv1);
    }
}

// ---------------------------------------------------------------------------
extern "C" void kernel_launch(void* const* d_in, const int* in_sizes, int n_in,
                              void* d_out, int out_size)
{
    const float* x    = (const float*)d_in[0];   // [4,1024,1024]
    const int*   mask = (const int*)  d_in[1];   // [4,1024]
    const float* W    = (const float*)d_in[2];   // [1024,3072]
    const float* bias = (const float*)d_in[3];   // [3072]
    float* out = (float*)d_out;                  // [4,1024,1024]

    cudaFuncSetAttribute(qkv_mma_kernel,
                         cudaFuncAttributeMaxDynamicSharedMemorySize, GEMM_SMEM);
    cudaFuncSetAttribute(attn_mma_kernel,
                         cudaFuncAttributeMaxDynamicSharedMemorySize, ATTN_SMEM);

    xconv_kernel<<<(MROWS * DIM) / (256 * 4), 256>>>(x);
    wconv_kernel<<<dim3(NCOLS / 32, DIM / 32), 256>>>(W);

    dim3 gg(NCOLS / 128, MROWS / 128);           // (24, 32)
    qkv_mma_kernel<<<gg, 256, GEMM_SMEM>>>(bias);

    dim3 ga(SEQ / 128, BATCH * NH);              // (8, 64)
    attn_mma_kernel<<<ga, 256, ATTN_SMEM>>>(mask, out);
}